// round 1
// baseline (speedup 1.0000x reference)
#include <cuda_runtime.h>
#include <cstdint>

#define B_S  256          // B*S
#define P_N  64           // prototypes
#define V_N  2562         // vertices
#define VT   128          // vertices per CTA tile
#define BSB  16           // bs per CTA tile
#define RSTR 20           // floats per (bs,p) record in g_R (duplicated pairs, padded)

// Scratch (static device globals; no allocation at runtime)
__device__ float g_R[(size_t)B_S * P_N * RSTR];   // ~1.3 MB
__device__ float g_Mt[B_S * 12];                  // Msum(9) + trans(3) per bs

// packed f32x2 helpers (sm_103a)
#define FMA2(acc, a, b) \
    asm("fma.rn.f32x2 %0, %1, %2, %0;" : "+l"(acc) : "l"(a), "l"(b))
#define UNPK(lo, hi, v) \
    asm("mov.b64 {%0,%1}, %2;" : "=f"(lo), "=f"(hi) : "l"(v))

// ---------------------------------------------------------------------------
// Kernel 1: per (bs,p) build Rws = EulerXYZ(rot)*w*scale (duplicated-pair
// layout for f32x2 consumption), and reduce Msum = sum_p Rws, trans = sum_p w*t.
// ---------------------------------------------------------------------------
__global__ __launch_bounds__(P_N) void rot_kernel(
    const float* __restrict__ scales,
    const float* __restrict__ transforms,
    const float* __restrict__ pw)
{
    const int bs = blockIdx.x;
    const int p  = threadIdx.x;

    const float* t = transforms + ((size_t)bs * P_N + p) * 6;
    const float tx = t[0], ty = t[1], tz = t[2];
    const float a0 = t[3], a1 = t[4], a2 = t[5];
    const float w  = pw[bs * P_N + p];
    const float ws = w * scales[bs];

    float sx, cx, sy, cy, sz, cz;
    sincosf(a0, &sx, &cx);
    sincosf(a1, &sy, &cy);
    sincosf(a2, &sz, &cz);

    // R = Rx(a0) @ Ry(a1) @ Rz(a2)
    float m00 = cy*cz,            m01 = -cy*sz,           m02 = sy;
    float m10 = cx*sz + sx*sy*cz, m11 = cx*cz - sx*sy*sz, m12 = -sx*cy;
    float m20 = sx*sz - cx*sy*cz, m21 = sx*cz + cx*sy*sz, m22 = cx*cy;
    m00*=ws; m01*=ws; m02*=ws;
    m10*=ws; m11*=ws; m12*=ws;
    m20*=ws; m21*=ws; m22*=ws;

    float4* o = (float4*)(g_R + ((size_t)bs * P_N + p) * RSTR);
    o[0] = make_float4(m00, m00, m01, m01);
    o[1] = make_float4(m02, m02, m10, m10);
    o[2] = make_float4(m11, m11, m12, m12);
    o[3] = make_float4(m20, m20, m21, m21);
    o[4] = make_float4(m22, m22, 0.f, 0.f);

    __shared__ float red[P_N][12];
    red[p][0]=m00; red[p][1]=m01; red[p][2]=m02;
    red[p][3]=m10; red[p][4]=m11; red[p][5]=m12;
    red[p][6]=m20; red[p][7]=m21; red[p][8]=m22;
    red[p][9]=w*tx; red[p][10]=w*ty; red[p][11]=w*tz;
    __syncthreads();
    if (p < 12) {
        float s = 0.f;
        for (int i = 0; i < P_N; ++i) s += red[i][p];
        g_Mt[bs*12 + p] = s;
    }
}

// ---------------------------------------------------------------------------
// Kernel 2: out[bs,v,:] = sum_p Rws[bs,p] @ off[p,v] + Msum[bs] @ base[v] + trans[bs]
// CTA = (v-tile of 128, bs-block of 16). 8 warps, warp handles one bs per pass
// (2 passes). Lane owns 4 consecutive vertices; inner math is packed f32x2.
// ---------------------------------------------------------------------------
#define SMEM_FLOATS (3*P_N*VT + BSB*P_N*RSTR + BSB*12)
#define SMEM_BYTES  (SMEM_FLOATS * 4)

__global__ __launch_bounds__(256, 1) void mesh_kernel(
    const float* __restrict__ off,   // (P,V,3)
    const float* __restrict__ base,  // (V,3)
    float* __restrict__ out)         // (B*S, V, 3)
{
    extern __shared__ float sm[];
    float* s_off = sm;                       // [3][P][VT]
    float* s_R   = sm + 3*P_N*VT;            // [BSB][P][RSTR]
    float* s_Mt  = s_R + BSB*P_N*RSTR;       // [BSB][12]

    const int tid   = threadIdx.x;
    const int vtile = blockIdx.x;
    const int bsb   = blockIdx.y;
    const int v0    = vtile * VT;
    const int nv    = min(VT, V_N - v0);

    // ---- stage Rws block ----
    {
        const float4* gR4 = (const float4*)(g_R + (size_t)bsb * BSB * P_N * RSTR);
        float4* sR4 = (float4*)s_R;
        #pragma unroll 4
        for (int i = tid; i < BSB * P_N * (RSTR/4); i += 256) sR4[i] = gR4[i];
        if (tid < BSB * 12) s_Mt[tid] = g_Mt[bsb * BSB * 12 + tid];
    }

    // ---- stage offsets tile, transposed (p,v,c) -> [c][p][v], zero-padded ----
    {
        // 192 float2 per p covering (v0..v0+VT)x3 components
        for (int i = tid; i < P_N * 192; i += 256) {
            const int p = i / 192;
            const int r = i - p * 192;
            const int f = 2 * r;                 // local float index, 0..383
            const int vA = f / 3,  cA = f  - 3 * vA;
            const int f1 = f + 1;
            const int vB = f1 / 3, cB = f1 - 3 * vB;
            float e0, e1;
            if (vB < nv) {
                const float2 d = *(const float2*)(off + ((size_t)p * V_N + v0) * 3 + f);
                e0 = d.x; e1 = d.y;
            } else {
                e0 = (vA < nv) ? off[((size_t)p * V_N + v0 + vA) * 3 + cA] : 0.f;
                e1 = 0.f;
            }
            s_off[(cA * P_N + p) * VT + vA] = e0;
            s_off[(cB * P_N + p) * VT + vB] = e1;
        }
    }
    __syncthreads();

    const int lane = tid & 31;
    const int warp = tid >> 5;
    const int vloc = lane * 4;

    // base verts for my 4 vertices (kept in registers across both bs passes)
    float bx[4], by[4], bz[4];
    #pragma unroll
    for (int k = 0; k < 4; ++k) {
        const int v = v0 + vloc + k;
        if (v < V_N) {
            bx[k] = base[v*3+0]; by[k] = base[v*3+1]; bz[k] = base[v*3+2];
        } else { bx[k] = by[k] = bz[k] = 0.f; }
    }

    const bool full = (v0 + VT <= V_N);

    for (int pass = 0; pass < 2; ++pass) {
        const int bsl = warp + pass * 8;      // local bs in [0,16)

        unsigned long long ax0=0ull, ax1=0ull, ay0=0ull, ay1=0ull, az0=0ull, az1=0ull;
        const float* Rbs = s_R + (size_t)bsl * P_N * RSTR;

        #pragma unroll 4
        for (int p = 0; p < P_N; ++p) {
            const float* ob = s_off + p * VT + vloc;
            const ulonglong2 ox = *(const ulonglong2*)(ob);
            const ulonglong2 oy = *(const ulonglong2*)(ob + P_N * VT);
            const ulonglong2 oz = *(const ulonglong2*)(ob + 2 * P_N * VT);

            const float* Rp = Rbs + p * RSTR;
            const ulonglong2 rA = *(const ulonglong2*)(Rp);       // m00 m01 (dup pairs)
            const ulonglong2 rB = *(const ulonglong2*)(Rp + 4);   // m02 m10
            const ulonglong2 rC = *(const ulonglong2*)(Rp + 8);   // m11 m12
            const ulonglong2 rD = *(const ulonglong2*)(Rp + 12);  // m20 m21
            const unsigned long long rE = *(const unsigned long long*)(Rp + 16); // m22

            FMA2(ax0, rA.x, ox.x); FMA2(ax0, rA.y, oy.x); FMA2(ax0, rB.x, oz.x);
            FMA2(ax1, rA.x, ox.y); FMA2(ax1, rA.y, oy.y); FMA2(ax1, rB.x, oz.y);
            FMA2(ay0, rB.y, ox.x); FMA2(ay0, rC.x, oy.x); FMA2(ay0, rC.y, oz.x);
            FMA2(ay1, rB.y, ox.y); FMA2(ay1, rC.x, oy.y); FMA2(ay1, rC.y, oz.y);
            FMA2(az0, rD.x, ox.x); FMA2(az0, rD.y, oy.x); FMA2(az0, rE,   oz.x);
            FMA2(az1, rD.x, ox.y); FMA2(az1, rD.y, oy.y); FMA2(az1, rE,   oz.y);
        }

        // epilogue: + Msum @ base + trans
        float ax[4], ay[4], az[4];
        UNPK(ax[0], ax[1], ax0); UNPK(ax[2], ax[3], ax1);
        UNPK(ay[0], ay[1], ay0); UNPK(ay[2], ay[3], ay1);
        UNPK(az[0], az[1], az0); UNPK(az[2], az[3], az1);

        const float* mt = s_Mt + bsl * 12;
        const float M0 = mt[0], M1 = mt[1], M2 = mt[2];
        const float M3 = mt[3], M4 = mt[4], M5 = mt[5];
        const float M6 = mt[6], M7 = mt[7], M8 = mt[8];
        const float T0 = mt[9], T1 = mt[10], T2 = mt[11];

        float r[12];
        #pragma unroll
        for (int k = 0; k < 4; ++k) {
            r[3*k+0] = ax[k] + M0*bx[k] + M1*by[k] + M2*bz[k] + T0;
            r[3*k+1] = ay[k] + M3*bx[k] + M4*by[k] + M5*bz[k] + T1;
            r[3*k+2] = az[k] + M6*bx[k] + M7*by[k] + M8*bz[k] + T2;
        }

        const int gbs = bsb * BSB + bsl;
        const size_t obase = ((size_t)gbs * V_N + v0 + vloc) * 3;
        if (full) {
            float2* o2 = (float2*)(out + obase);  // 8B-aligned (index always even)
            #pragma unroll
            for (int j = 0; j < 6; ++j) o2[j] = make_float2(r[2*j], r[2*j+1]);
        } else {
            #pragma unroll
            for (int k = 0; k < 4; ++k) {
                if (v0 + vloc + k < V_N) {
                    out[obase + 3*k + 0] = r[3*k+0];
                    out[obase + 3*k + 1] = r[3*k+1];
                    out[obase + 3*k + 2] = r[3*k+2];
                }
            }
        }
    }
}

// ---------------------------------------------------------------------------
extern "C" void kernel_launch(void* const* d_in, const int* in_sizes, int n_in,
                              void* d_out, int out_size)
{
    (void)in_sizes; (void)n_in; (void)out_size;
    const float* scales     = (const float*)d_in[0];  // (B,S,1)
    const float* transforms = (const float*)d_in[1];  // (B,S,P,6)
    const float* pw         = (const float*)d_in[2];  // (B,S,P)
    const float* off        = (const float*)d_in[3];  // (P,V,3)
    const float* base       = (const float*)d_in[4];  // (V,3)
    float* out = (float*)d_out;

    rot_kernel<<<B_S, P_N>>>(scales, transforms, pw);

    cudaFuncSetAttribute(mesh_kernel,
                         cudaFuncAttributeMaxDynamicSharedMemorySize, SMEM_BYTES);
    dim3 grid((V_N + VT - 1) / VT, B_S / BSB);   // (21, 16)
    mesh_kernel<<<grid, 256, SMEM_BYTES>>>(off, base, out);
}

// round 2
// speedup vs baseline: 1.5411x; 1.5411x over previous
#include <cuda_runtime.h>
#include <cstdint>

#define B_S  256          // B*S
#define P_N  64           // prototypes
#define V_N  2562         // vertices
#define VT   128          // vertices per CTA tile
#define BSB  16           // bs per CTA tile
#define RSTR 20           // floats per (bs,p) record in g_R (duplicated pairs, padded)

// Scratch (static device globals; no allocation at runtime)
__device__ float g_R[(size_t)B_S * P_N * RSTR];   // ~1.3 MB
__device__ float g_Mt[B_S * 12];                  // Msum(9) + trans(3) per bs

// packed f32x2 helpers (sm_103a)
#define FMA2(acc, a, b) \
    asm("fma.rn.f32x2 %0, %1, %2, %0;" : "+l"(acc) : "l"(a), "l"(b))
#define UNPK(lo, hi, v) \
    asm("mov.b64 {%0,%1}, %2;" : "=f"(lo), "=f"(hi) : "l"(v))

// ---------------------------------------------------------------------------
// Kernel 1: per (bs,p) build Rws = EulerXYZ(rot)*w*scale (duplicated-pair
// layout for f32x2 consumption), and reduce Msum = sum_p Rws, trans = sum_p w*t.
// ---------------------------------------------------------------------------
__global__ __launch_bounds__(P_N) void rot_kernel(
    const float* __restrict__ scales,
    const float* __restrict__ transforms,
    const float* __restrict__ pw)
{
    const int bs = blockIdx.x;
    const int p  = threadIdx.x;

    const float* t = transforms + ((size_t)bs * P_N + p) * 6;
    const float tx = t[0], ty = t[1], tz = t[2];
    const float a0 = t[3], a1 = t[4], a2 = t[5];
    const float w  = pw[bs * P_N + p];
    const float ws = w * scales[bs];

    float sx, cx, sy, cy, sz, cz;
    sincosf(a0, &sx, &cx);
    sincosf(a1, &sy, &cy);
    sincosf(a2, &sz, &cz);

    // R = Rx(a0) @ Ry(a1) @ Rz(a2)
    float m00 = cy*cz,            m01 = -cy*sz,           m02 = sy;
    float m10 = cx*sz + sx*sy*cz, m11 = cx*cz - sx*sy*sz, m12 = -sx*cy;
    float m20 = sx*sz - cx*sy*cz, m21 = sx*cz + cx*sy*sz, m22 = cx*cy;
    m00*=ws; m01*=ws; m02*=ws;
    m10*=ws; m11*=ws; m12*=ws;
    m20*=ws; m21*=ws; m22*=ws;

    float4* o = (float4*)(g_R + ((size_t)bs * P_N + p) * RSTR);
    o[0] = make_float4(m00, m00, m01, m01);
    o[1] = make_float4(m02, m02, m10, m10);
    o[2] = make_float4(m11, m11, m12, m12);
    o[3] = make_float4(m20, m20, m21, m21);
    o[4] = make_float4(m22, m22, 0.f, 0.f);

    __shared__ float red[P_N][12];
    red[p][0]=m00; red[p][1]=m01; red[p][2]=m02;
    red[p][3]=m10; red[p][4]=m11; red[p][5]=m12;
    red[p][6]=m20; red[p][7]=m21; red[p][8]=m22;
    red[p][9]=w*tx; red[p][10]=w*ty; red[p][11]=w*tz;
    __syncthreads();
    if (p < 12) {
        float s = 0.f;
        for (int i = 0; i < P_N; ++i) s += red[i][p];
        g_Mt[bs*12 + p] = s;
    }
}

// ---------------------------------------------------------------------------
// Kernel 2: out[bs,v,:] = sum_p Rws[bs,p] @ off[p,v] + Msum[bs] @ base[v] + trans[bs]
// CTA = (v-tile of 128, bs-block of 16). 8 warps; each warp processes TWO bs
// (warp, warp+8) in a single fused p-loop: off loads amortized over 2 bs,
// 12 independent FMA chains for latency hiding. Lane owns 4 vertices.
// ---------------------------------------------------------------------------
#define SMEM_FLOATS (3*P_N*VT + BSB*P_N*RSTR + BSB*12)
#define SMEM_BYTES  (SMEM_FLOATS * 4)

__global__ __launch_bounds__(256, 1) void mesh_kernel(
    const float* __restrict__ off,   // (P,V,3)
    const float* __restrict__ base,  // (V,3)
    float* __restrict__ out)         // (B*S, V, 3)
{
    extern __shared__ float sm[];
    float* s_off = sm;                       // [3][P][VT]
    float* s_R   = sm + 3*P_N*VT;            // [BSB][P][RSTR]
    float* s_Mt  = s_R + BSB*P_N*RSTR;       // [BSB][12]

    const int tid   = threadIdx.x;
    const int vtile = blockIdx.x;
    const int bsb   = blockIdx.y;
    const int v0    = vtile * VT;
    const int nv    = min(VT, V_N - v0);

    // ---- stage Rws block ----
    {
        const float4* gR4 = (const float4*)(g_R + (size_t)bsb * BSB * P_N * RSTR);
        float4* sR4 = (float4*)s_R;
        #pragma unroll 4
        for (int i = tid; i < BSB * P_N * (RSTR/4); i += 256) sR4[i] = gR4[i];
        if (tid < BSB * 12) s_Mt[tid] = g_Mt[bsb * BSB * 12 + tid];
    }

    // ---- stage offsets tile, transposed (p,v,c) -> [c][p][v], zero-padded ----
    {
        for (int i = tid; i < P_N * 192; i += 256) {
            const int p = i / 192;
            const int r = i - p * 192;
            const int f = 2 * r;                 // local float index, 0..383
            const int vA = f / 3,  cA = f  - 3 * vA;
            const int f1 = f + 1;
            const int vB = f1 / 3, cB = f1 - 3 * vB;
            float e0, e1;
            if (vB < nv) {
                const float2 d = *(const float2*)(off + ((size_t)p * V_N + v0) * 3 + f);
                e0 = d.x; e1 = d.y;
            } else {
                e0 = (vA < nv) ? off[((size_t)p * V_N + v0 + vA) * 3 + cA] : 0.f;
                e1 = 0.f;
            }
            s_off[(cA * P_N + p) * VT + vA] = e0;
            s_off[(cB * P_N + p) * VT + vB] = e1;
        }
    }
    __syncthreads();

    const int lane = tid & 31;
    const int warp = tid >> 5;
    const int vloc = lane * 4;

    // base verts for my 4 vertices
    float bx[4], by[4], bz[4];
    #pragma unroll
    for (int k = 0; k < 4; ++k) {
        const int v = v0 + vloc + k;
        if (v < V_N) {
            bx[k] = base[v*3+0]; by[k] = base[v*3+1]; bz[k] = base[v*3+2];
        } else { bx[k] = by[k] = bz[k] = 0.f; }
    }

    const bool full = (v0 + VT <= V_N);

    // two bs per warp, one fused p-loop
    const int bsl0 = warp;
    const int bsl1 = warp + 8;
    const float* R0 = s_R + (size_t)bsl0 * P_N * RSTR;
    const float* R1 = s_R + (size_t)bsl1 * P_N * RSTR;

    unsigned long long Ax0=0, Ax1=0, Ay0=0, Ay1=0, Az0=0, Az1=0;   // bs0
    unsigned long long Bx0=0, Bx1=0, By0=0, By1=0, Bz0=0, Bz1=0;   // bs1

    #pragma unroll 2
    for (int p = 0; p < P_N; ++p) {
        const float* ob = s_off + p * VT + vloc;
        const ulonglong2 ox = *(const ulonglong2*)(ob);
        const ulonglong2 oy = *(const ulonglong2*)(ob + P_N * VT);
        const ulonglong2 oz = *(const ulonglong2*)(ob + 2 * P_N * VT);

        const float* Rp0 = R0 + p * RSTR;
        const ulonglong2 rA = *(const ulonglong2*)(Rp0);       // m00 m01
        const ulonglong2 rB = *(const ulonglong2*)(Rp0 + 4);   // m02 m10
        const ulonglong2 rC = *(const ulonglong2*)(Rp0 + 8);   // m11 m12
        const ulonglong2 rD = *(const ulonglong2*)(Rp0 + 12);  // m20 m21
        const unsigned long long rE = *(const unsigned long long*)(Rp0 + 16);

        const float* Rp1 = R1 + p * RSTR;
        const ulonglong2 qA = *(const ulonglong2*)(Rp1);
        const ulonglong2 qB = *(const ulonglong2*)(Rp1 + 4);
        const ulonglong2 qC = *(const ulonglong2*)(Rp1 + 8);
        const ulonglong2 qD = *(const ulonglong2*)(Rp1 + 12);
        const unsigned long long qE = *(const unsigned long long*)(Rp1 + 16);

        // bs0
        FMA2(Ax0, rA.x, ox.x); FMA2(Ax0, rA.y, oy.x); FMA2(Ax0, rB.x, oz.x);
        FMA2(Ax1, rA.x, ox.y); FMA2(Ax1, rA.y, oy.y); FMA2(Ax1, rB.x, oz.y);
        FMA2(Ay0, rB.y, ox.x); FMA2(Ay0, rC.x, oy.x); FMA2(Ay0, rC.y, oz.x);
        FMA2(Ay1, rB.y, ox.y); FMA2(Ay1, rC.x, oy.y); FMA2(Ay1, rC.y, oz.y);
        FMA2(Az0, rD.x, ox.x); FMA2(Az0, rD.y, oy.x); FMA2(Az0, rE,   oz.x);
        FMA2(Az1, rD.x, ox.y); FMA2(Az1, rD.y, oy.y); FMA2(Az1, rE,   oz.y);
        // bs1
        FMA2(Bx0, qA.x, ox.x); FMA2(Bx0, qA.y, oy.x); FMA2(Bx0, qB.x, oz.x);
        FMA2(Bx1, qA.x, ox.y); FMA2(Bx1, qA.y, oy.y); FMA2(Bx1, qB.x, oz.y);
        FMA2(By0, qB.y, ox.x); FMA2(By0, qC.x, oy.x); FMA2(By0, qC.y, oz.x);
        FMA2(By1, qB.y, ox.y); FMA2(By1, qC.x, oy.y); FMA2(By1, qC.y, oz.y);
        FMA2(Bz0, qD.x, ox.x); FMA2(Bz0, qD.y, oy.x); FMA2(Bz0, qE,   oz.x);
        FMA2(Bz1, qD.x, ox.y); FMA2(Bz1, qD.y, oy.y); FMA2(Bz1, qE,   oz.y);
    }

    // ---- epilogue for both bs ----
    #pragma unroll
    for (int half = 0; half < 2; ++half) {
        const int bsl = half ? bsl1 : bsl0;
        float ax[4], ay[4], az[4];
        if (half == 0) {
            UNPK(ax[0], ax[1], Ax0); UNPK(ax[2], ax[3], Ax1);
            UNPK(ay[0], ay[1], Ay0); UNPK(ay[2], ay[3], Ay1);
            UNPK(az[0], az[1], Az0); UNPK(az[2], az[3], Az1);
        } else {
            UNPK(ax[0], ax[1], Bx0); UNPK(ax[2], ax[3], Bx1);
            UNPK(ay[0], ay[1], By0); UNPK(ay[2], ay[3], By1);
            UNPK(az[0], az[1], Bz0); UNPK(az[2], az[3], Bz1);
        }

        const float* mt = s_Mt + bsl * 12;
        const float M0 = mt[0], M1 = mt[1], M2 = mt[2];
        const float M3 = mt[3], M4 = mt[4], M5 = mt[5];
        const float M6 = mt[6], M7 = mt[7], M8 = mt[8];
        const float T0 = mt[9], T1 = mt[10], T2 = mt[11];

        float r[12];
        #pragma unroll
        for (int k = 0; k < 4; ++k) {
            r[3*k+0] = ax[k] + M0*bx[k] + M1*by[k] + M2*bz[k] + T0;
            r[3*k+1] = ay[k] + M3*bx[k] + M4*by[k] + M5*bz[k] + T1;
            r[3*k+2] = az[k] + M6*bx[k] + M7*by[k] + M8*bz[k] + T2;
        }

        const int gbs = bsb * BSB + bsl;
        const size_t obase = ((size_t)gbs * V_N + v0 + vloc) * 3;
        if (full) {
            float2* o2 = (float2*)(out + obase);  // 8B-aligned (index always even)
            #pragma unroll
            for (int j = 0; j < 6; ++j) o2[j] = make_float2(r[2*j], r[2*j+1]);
        } else {
            #pragma unroll
            for (int k = 0; k < 4; ++k) {
                if (v0 + vloc + k < V_N) {
                    out[obase + 3*k + 0] = r[3*k+0];
                    out[obase + 3*k + 1] = r[3*k+1];
                    out[obase + 3*k + 2] = r[3*k+2];
                }
            }
        }
    }
}

// ---------------------------------------------------------------------------
extern "C" void kernel_launch(void* const* d_in, const int* in_sizes, int n_in,
                              void* d_out, int out_size)
{
    (void)in_sizes; (void)n_in; (void)out_size;
    const float* scales     = (const float*)d_in[0];  // (B,S,1)
    const float* transforms = (const float*)d_in[1];  // (B,S,P,6)
    const float* pw         = (const float*)d_in[2];  // (B,S,P)
    const float* off        = (const float*)d_in[3];  // (P,V,3)
    const float* base       = (const float*)d_in[4];  // (V,3)
    float* out = (float*)d_out;

    rot_kernel<<<B_S, P_N>>>(scales, transforms, pw);

    cudaFuncSetAttribute(mesh_kernel,
                         cudaFuncAttributeMaxDynamicSharedMemorySize, SMEM_BYTES);
    dim3 grid((V_N + VT - 1) / VT, B_S / BSB);   // (21, 16)
    mesh_kernel<<<grid, 256, SMEM_BYTES>>>(off, base, out);
}

// round 3
// speedup vs baseline: 2.3699x; 1.5378x over previous
#include <cuda_runtime.h>
#include <cstdint>

#define B_S   256         // B*S
#define P_N   64          // prototypes
#define V_N   2562        // vertices
#define VT    128         // vertices per CTA tile
#define BSB   32          // bs per CTA tile
#define NPAIR 16          // bs-pairs per CTA ( = warps )
#define RSTR  20          // floats per (pair,p) record: 9 float-pairs + pad

// Scratch (static device globals; no runtime allocation)
__device__ float g_R[(size_t)(B_S/2) * P_N * RSTR];  // pair-interleaved, ~655KB
__device__ float g_Mt[B_S * 12];                     // Msum(9) + trans(3) per bs

// packed f32x2 helpers (sm_103a)
#define FMA2(acc, a, b) \
    asm("fma.rn.f32x2 %0, %1, %2, %0;" : "+l"(acc) : "l"(a), "l"(b))
#define UNPK(lo, hi, v) \
    asm("mov.b64 {%0,%1}, %2;" : "=f"(lo), "=f"(hi) : "l"(v))
#define DUP(d, f) \
    asm("mov.b64 %0, {%1, %1};" : "=l"(d) : "f"(f))

// ---------------------------------------------------------------------------
// Kernel 1: per (bs,p) build Rws = EulerXYZ(rot)*w*scale. Write pair-interleaved:
// record for pair g = bs>>1 holds (even,odd) adjacent per matrix element, so one
// LDS.128 in kernel 2 yields two ready f32x2 operands. Also reduce Msum, trans.
// ---------------------------------------------------------------------------
__global__ __launch_bounds__(P_N) void rot_kernel(
    const float* __restrict__ scales,
    const float* __restrict__ transforms,
    const float* __restrict__ pw)
{
    const int bs = blockIdx.x;
    const int p  = threadIdx.x;

    const float* t = transforms + ((size_t)bs * P_N + p) * 6;
    const float tx = t[0], ty = t[1], tz = t[2];
    const float a0 = t[3], a1 = t[4], a2 = t[5];
    const float w  = pw[bs * P_N + p];
    const float ws = w * scales[bs];

    float sx, cx, sy, cy, sz, cz;
    sincosf(a0, &sx, &cx);
    sincosf(a1, &sy, &cy);
    sincosf(a2, &sz, &cz);

    // R = Rx(a0) @ Ry(a1) @ Rz(a2)
    float m00 = cy*cz,            m01 = -cy*sz,           m02 = sy;
    float m10 = cx*sz + sx*sy*cz, m11 = cx*cz - sx*sy*sz, m12 = -sx*cy;
    float m20 = sx*sz - cx*sy*cz, m21 = sx*cz + cx*sy*sz, m22 = cx*cy;
    m00*=ws; m01*=ws; m02*=ws;
    m10*=ws; m11*=ws; m12*=ws;
    m20*=ws; m21*=ws; m22*=ws;

    // pair-interleaved write: slot 2*m + (bs&1)
    float* o = g_R + ((size_t)(bs >> 1) * P_N + p) * RSTR + (bs & 1);
    o[0]  = m00; o[2]  = m01; o[4]  = m02;
    o[6]  = m10; o[8]  = m11; o[10] = m12;
    o[12] = m20; o[14] = m21; o[16] = m22;

    __shared__ float red[P_N][12];
    red[p][0]=m00; red[p][1]=m01; red[p][2]=m02;
    red[p][3]=m10; red[p][4]=m11; red[p][5]=m12;
    red[p][6]=m20; red[p][7]=m21; red[p][8]=m22;
    red[p][9]=w*tx; red[p][10]=w*ty; red[p][11]=w*tz;
    __syncthreads();
    if (p < 12) {
        float s = 0.f;
        for (int i = 0; i < P_N; ++i) s += red[i][p];
        g_Mt[bs*12 + p] = s;
    }
}

// ---------------------------------------------------------------------------
// Kernel 2: 512 threads. CTA = (v-tile 128, bs-block 32). Warp w owns bs pair
// (2w, 2w+1) of the block; f32x2 lanes pack (even bs, odd bs). Off operands
// duplicated via mov.b64; R pairs come straight out of smem via LDS.128.
// ---------------------------------------------------------------------------
#define SMEM_FLOATS (3*P_N*VT + NPAIR*P_N*RSTR + BSB*12)
#define SMEM_BYTES  (SMEM_FLOATS * 4)

__global__ __launch_bounds__(512, 1) void mesh_kernel(
    const float* __restrict__ off,   // (P,V,3)
    const float* __restrict__ base,  // (V,3)
    float* __restrict__ out)         // (B*S, V, 3)
{
    extern __shared__ float sm[];
    float* s_off = sm;                       // [3][P][VT]
    float* s_R   = sm + 3*P_N*VT;            // [NPAIR][P][RSTR]
    float* s_Mt  = s_R + NPAIR*P_N*RSTR;     // [BSB][12]

    const int tid   = threadIdx.x;
    const int vtile = blockIdx.x;
    const int bsb   = blockIdx.y;
    const int v0    = vtile * VT;
    const int nv    = min(VT, V_N - v0);

    // ---- stage R pair block (16 pairs x 64 p x 20 floats = 80KB) ----
    {
        const float4* gR4 = (const float4*)(g_R + (size_t)bsb * NPAIR * P_N * RSTR);
        float4* sR4 = (float4*)s_R;
        #pragma unroll
        for (int i = tid; i < NPAIR * P_N * (RSTR/4); i += 512) sR4[i] = gR4[i];
        if (tid < BSB * 12) s_Mt[tid] = g_Mt[bsb * BSB * 12 + tid];
    }

    // ---- stage offsets tile, transposed (p,v,c) -> [c][p][v], zero-padded ----
    {
        for (int i = tid; i < P_N * 192; i += 512) {
            const int p = i / 192;
            const int r = i - p * 192;
            const int f = 2 * r;                 // local float index, 0..383
            const int vA = f / 3,  cA = f  - 3 * vA;
            const int f1 = f + 1;
            const int vB = f1 / 3, cB = f1 - 3 * vB;
            float e0, e1;
            if (vB < nv) {
                const float2 d = *(const float2*)(off + ((size_t)p * V_N + v0) * 3 + f);
                e0 = d.x; e1 = d.y;
            } else {
                e0 = (vA < nv) ? off[((size_t)p * V_N + v0 + vA) * 3 + cA] : 0.f;
                e1 = 0.f;
            }
            s_off[(cA * P_N + p) * VT + vA] = e0;
            s_off[(cB * P_N + p) * VT + vB] = e1;
        }
    }
    __syncthreads();

    const int lane = tid & 31;
    const int warp = tid >> 5;           // 0..15 = pair index within block
    const int vloc = lane * 4;

    // base verts for my 4 vertices
    float bx[4], by[4], bz[4];
    #pragma unroll
    for (int k = 0; k < 4; ++k) {
        const int v = v0 + vloc + k;
        if (v < V_N) {
            bx[k] = base[v*3+0]; by[k] = base[v*3+1]; bz[k] = base[v*3+2];
        } else { bx[k] = by[k] = bz[k] = 0.f; }
    }

    const bool full = (v0 + VT <= V_N);
    const float* Rp_base = s_R + (size_t)warp * P_N * RSTR;

    // accumulators: [vert][comp], each f32x2 = (bs_even, bs_odd)
    unsigned long long aX[4] = {0,0,0,0};
    unsigned long long aY[4] = {0,0,0,0};
    unsigned long long aZ[4] = {0,0,0,0};

    #pragma unroll 2
    for (int p = 0; p < P_N; ++p) {
        // off for my 4 verts, 3 comps
        const float* ob = s_off + p * VT + vloc;
        const float4 ox = *(const float4*)(ob);
        const float4 oy = *(const float4*)(ob + P_N * VT);
        const float4 oz = *(const float4*)(ob + 2 * P_N * VT);

        // R pairs (broadcast LDS.128): each .x/.y is a ready f32x2 (even,odd)
        const float* Rp = Rp_base + p * RSTR;
        const ulonglong2 rA = *(const ulonglong2*)(Rp);       // m00 | m01
        const ulonglong2 rB = *(const ulonglong2*)(Rp + 4);   // m02 | m10
        const ulonglong2 rC = *(const ulonglong2*)(Rp + 8);   // m11 | m12
        const ulonglong2 rD = *(const ulonglong2*)(Rp + 12);  // m20 | m21
        const unsigned long long rE = *(const unsigned long long*)(Rp + 16); // m22

        // duplicate off values into f32x2 operands
        unsigned long long dx[4], dy[4], dz[4];
        DUP(dx[0], ox.x); DUP(dx[1], ox.y); DUP(dx[2], ox.z); DUP(dx[3], ox.w);
        DUP(dy[0], oy.x); DUP(dy[1], oy.y); DUP(dy[2], oy.z); DUP(dy[3], oy.w);
        DUP(dz[0], oz.x); DUP(dz[1], oz.y); DUP(dz[2], oz.z); DUP(dz[3], oz.w);

        #pragma unroll
        for (int k = 0; k < 4; ++k) {
            FMA2(aX[k], rA.x, dx[k]); FMA2(aX[k], rA.y, dy[k]); FMA2(aX[k], rB.x, dz[k]);
            FMA2(aY[k], rB.y, dx[k]); FMA2(aY[k], rC.x, dy[k]); FMA2(aY[k], rC.y, dz[k]);
            FMA2(aZ[k], rD.x, dx[k]); FMA2(aZ[k], rD.y, dy[k]); FMA2(aZ[k], rE,   dz[k]);
        }
    }

    // ---- epilogue: split pair halves, add Msum @ base + trans, store ----
    #pragma unroll
    for (int par = 0; par < 2; ++par) {
        float ax[4], ay[4], az[4];
        #pragma unroll
        for (int k = 0; k < 4; ++k) {
            float e, o_;
            UNPK(e, o_, aX[k]); ax[k] = par ? o_ : e;
            UNPK(e, o_, aY[k]); ay[k] = par ? o_ : e;
            UNPK(e, o_, aZ[k]); az[k] = par ? o_ : e;
        }

        const int bsl = 2 * warp + par;            // local bs in [0,32)
        const float* mt = s_Mt + bsl * 12;
        const float M0 = mt[0], M1 = mt[1], M2 = mt[2];
        const float M3 = mt[3], M4 = mt[4], M5 = mt[5];
        const float M6 = mt[6], M7 = mt[7], M8 = mt[8];
        const float T0 = mt[9], T1 = mt[10], T2 = mt[11];

        float r[12];
        #pragma unroll
        for (int k = 0; k < 4; ++k) {
            r[3*k+0] = ax[k] + M0*bx[k] + M1*by[k] + M2*bz[k] + T0;
            r[3*k+1] = ay[k] + M3*bx[k] + M4*by[k] + M5*bz[k] + T1;
            r[3*k+2] = az[k] + M6*bx[k] + M7*by[k] + M8*bz[k] + T2;
        }

        const int gbs = bsb * BSB + bsl;
        const size_t obase = ((size_t)gbs * V_N + v0 + vloc) * 3;
        if (full) {
            float2* o2 = (float2*)(out + obase);   // 8B-aligned (index always even)
            #pragma unroll
            for (int j = 0; j < 6; ++j) o2[j] = make_float2(r[2*j], r[2*j+1]);
        } else {
            #pragma unroll
            for (int k = 0; k < 4; ++k) {
                if (v0 + vloc + k < V_N) {
                    out[obase + 3*k + 0] = r[3*k+0];
                    out[obase + 3*k + 1] = r[3*k+1];
                    out[obase + 3*k + 2] = r[3*k+2];
                }
            }
        }
    }
}

// ---------------------------------------------------------------------------
extern "C" void kernel_launch(void* const* d_in, const int* in_sizes, int n_in,
                              void* d_out, int out_size)
{
    (void)in_sizes; (void)n_in; (void)out_size;
    const float* scales     = (const float*)d_in[0];  // (B,S,1)
    const float* transforms = (const float*)d_in[1];  // (B,S,P,6)
    const float* pw         = (const float*)d_in[2];  // (B,S,P)
    const float* off        = (const float*)d_in[3];  // (P,V,3)
    const float* base       = (const float*)d_in[4];  // (V,3)
    float* out = (float*)d_out;

    rot_kernel<<<B_S, P_N>>>(scales, transforms, pw);

    cudaFuncSetAttribute(mesh_kernel,
                         cudaFuncAttributeMaxDynamicSharedMemorySize, SMEM_BYTES);
    dim3 grid((V_N + VT - 1) / VT, B_S / BSB);   // (21, 8)
    mesh_kernel<<<grid, 512, SMEM_BYTES>>>(off, base, out);
}

// round 4
// speedup vs baseline: 2.6322x; 1.1107x over previous
#include <cuda_runtime.h>
#include <cstdint>

#define B_S   256         // B*S
#define P_N   64          // prototypes
#define V_N   2562        // vertices
#define VT    64          // vertices per CTA tile
#define BSB   16          // bs per CTA tile (= 8 pairs = 8 warps)
#define NPAIR 8           // bs-pairs per CTA
#define RSTR  20          // floats per (pair,p) record: 9 float-pairs + pad

// Scratch (static device globals; no runtime allocation)
__device__ float g_R[(size_t)(B_S/2) * P_N * RSTR];  // pair-interleaved, ~655KB
__device__ float g_Mt[B_S * 12];                     // Msum(9) + trans(3) per bs

// packed f32x2 helpers (sm_103a)
#define FMA2(acc, a, b) \
    asm("fma.rn.f32x2 %0, %1, %2, %0;" : "+l"(acc) : "l"(a), "l"(b))
#define UNPK(lo, hi, v) \
    asm("mov.b64 {%0,%1}, %2;" : "=f"(lo), "=f"(hi) : "l"(v))
#define DUP(d, f) \
    asm("mov.b64 %0, {%1, %1};" : "=l"(d) : "f"(f))

// ---------------------------------------------------------------------------
// Kernel 1: per (bs,p) build Rws = EulerXYZ(rot)*w*scale. Pair-interleaved
// layout: record for pair g=bs>>1 holds (even,odd) adjacent per element, so
// one LDS.128 in kernel 2 yields two ready f32x2 operands. Also Msum, trans.
// ---------------------------------------------------------------------------
__global__ __launch_bounds__(P_N) void rot_kernel(
    const float* __restrict__ scales,
    const float* __restrict__ transforms,
    const float* __restrict__ pw)
{
    const int bs = blockIdx.x;
    const int p  = threadIdx.x;

    const float* t = transforms + ((size_t)bs * P_N + p) * 6;
    const float tx = t[0], ty = t[1], tz = t[2];
    const float a0 = t[3], a1 = t[4], a2 = t[5];
    const float w  = pw[bs * P_N + p];
    const float ws = w * scales[bs];

    float sx, cx, sy, cy, sz, cz;
    sincosf(a0, &sx, &cx);
    sincosf(a1, &sy, &cy);
    sincosf(a2, &sz, &cz);

    // R = Rx(a0) @ Ry(a1) @ Rz(a2)
    float m00 = cy*cz,            m01 = -cy*sz,           m02 = sy;
    float m10 = cx*sz + sx*sy*cz, m11 = cx*cz - sx*sy*sz, m12 = -sx*cy;
    float m20 = sx*sz - cx*sy*cz, m21 = sx*cz + cx*sy*sz, m22 = cx*cy;
    m00*=ws; m01*=ws; m02*=ws;
    m10*=ws; m11*=ws; m12*=ws;
    m20*=ws; m21*=ws; m22*=ws;

    // pair-interleaved write: slot 2*m + (bs&1)
    float* o = g_R + ((size_t)(bs >> 1) * P_N + p) * RSTR + (bs & 1);
    o[0]  = m00; o[2]  = m01; o[4]  = m02;
    o[6]  = m10; o[8]  = m11; o[10] = m12;
    o[12] = m20; o[14] = m21; o[16] = m22;

    __shared__ float red[P_N][12];
    red[p][0]=m00; red[p][1]=m01; red[p][2]=m02;
    red[p][3]=m10; red[p][4]=m11; red[p][5]=m12;
    red[p][6]=m20; red[p][7]=m21; red[p][8]=m22;
    red[p][9]=w*tx; red[p][10]=w*ty; red[p][11]=w*tz;
    __syncthreads();
    if (p < 12) {
        float s = 0.f;
        for (int i = 0; i < P_N; ++i) s += red[i][p];
        g_Mt[bs*12 + p] = s;
    }
}

// ---------------------------------------------------------------------------
// Kernel 2: 256 threads, 2 CTAs/SM. CTA = (v-tile 64, bs-block 16). Warp w
// owns bs pair (2w, 2w+1); f32x2 lanes pack (even bs, odd bs). Lane owns 2
// verts. Small CTAs: grid 656 -> wave-balanced, staging overlapped across
// the two resident CTAs.
// ---------------------------------------------------------------------------
#define SMEM_FLOATS (3*P_N*VT + NPAIR*P_N*RSTR + BSB*12)
#define SMEM_BYTES  (SMEM_FLOATS * 4)

__global__ __launch_bounds__(256, 2) void mesh_kernel(
    const float* __restrict__ off,   // (P,V,3)
    const float* __restrict__ base,  // (V,3)
    float* __restrict__ out)         // (B*S, V, 3)
{
    extern __shared__ float sm[];
    float* s_off = sm;                       // [3][P][VT]
    float* s_R   = sm + 3*P_N*VT;            // [NPAIR][P][RSTR]
    float* s_Mt  = s_R + NPAIR*P_N*RSTR;     // [BSB][12]

    const int tid   = threadIdx.x;
    const int vtile = blockIdx.x;
    const int bsb   = blockIdx.y;
    const int v0    = vtile * VT;
    const int nv    = min(VT, V_N - v0);

    // ---- stage R pair block (8 pairs x 64 p x 20 floats = 40KB) ----
    {
        const float4* gR4 = (const float4*)(g_R + (size_t)bsb * NPAIR * P_N * RSTR);
        float4* sR4 = (float4*)s_R;
        #pragma unroll
        for (int i = tid; i < NPAIR * P_N * (RSTR/4); i += 256) sR4[i] = gR4[i];
        if (tid < BSB * 12) s_Mt[tid] = g_Mt[bsb * BSB * 12 + tid];
    }

    // ---- stage offsets tile, transposed (p,v,c) -> [c][p][v], zero-padded ----
    {
        // 96 float2 per p covering (v0..v0+VT)x3 components (192 floats)
        for (int i = tid; i < P_N * 96; i += 256) {
            const int p = i / 96;
            const int r = i - p * 96;
            const int f = 2 * r;                 // local float index, 0..190
            const int vA = f / 3,  cA = f  - 3 * vA;
            const int f1 = f + 1;
            const int vB = f1 / 3, cB = f1 - 3 * vB;
            float e0, e1;
            if (vB < nv) {
                const float2 d = *(const float2*)(off + ((size_t)p * V_N + v0) * 3 + f);
                e0 = d.x; e1 = d.y;
            } else {
                e0 = (vA < nv) ? off[((size_t)p * V_N + v0 + vA) * 3 + cA] : 0.f;
                e1 = 0.f;
            }
            s_off[(cA * P_N + p) * VT + vA] = e0;
            s_off[(cB * P_N + p) * VT + vB] = e1;
        }
    }
    __syncthreads();

    const int lane = tid & 31;
    const int warp = tid >> 5;           // 0..7 = pair index within block
    const int vloc = lane * 2;

    // base verts for my 2 vertices
    float bx[2], by[2], bz[2];
    #pragma unroll
    for (int k = 0; k < 2; ++k) {
        const int v = v0 + vloc + k;
        if (v < V_N) {
            bx[k] = base[v*3+0]; by[k] = base[v*3+1]; bz[k] = base[v*3+2];
        } else { bx[k] = by[k] = bz[k] = 0.f; }
    }

    const bool full = (v0 + VT <= V_N);
    const float* Rp_base = s_R + (size_t)warp * P_N * RSTR;

    // accumulators: [vert][comp], each f32x2 = (bs_even, bs_odd)
    unsigned long long aX[2] = {0,0};
    unsigned long long aY[2] = {0,0};
    unsigned long long aZ[2] = {0,0};

    #pragma unroll 4
    for (int p = 0; p < P_N; ++p) {
        // off for my 2 verts, 3 comps (LDS.64 each, conflict-free)
        const float* ob = s_off + p * VT + vloc;
        const float2 ox = *(const float2*)(ob);
        const float2 oy = *(const float2*)(ob + P_N * VT);
        const float2 oz = *(const float2*)(ob + 2 * P_N * VT);

        // R pairs (broadcast LDS): each .x/.y is a ready f32x2 (even,odd)
        const float* Rp = Rp_base + p * RSTR;
        const ulonglong2 rA = *(const ulonglong2*)(Rp);       // m00 | m01
        const ulonglong2 rB = *(const ulonglong2*)(Rp + 4);   // m02 | m10
        const ulonglong2 rC = *(const ulonglong2*)(Rp + 8);   // m11 | m12
        const ulonglong2 rD = *(const ulonglong2*)(Rp + 12);  // m20 | m21
        const unsigned long long rE = *(const unsigned long long*)(Rp + 16); // m22

        // duplicate off values into f32x2 operands
        unsigned long long dx[2], dy[2], dz[2];
        DUP(dx[0], ox.x); DUP(dx[1], ox.y);
        DUP(dy[0], oy.x); DUP(dy[1], oy.y);
        DUP(dz[0], oz.x); DUP(dz[1], oz.y);

        #pragma unroll
        for (int k = 0; k < 2; ++k) {
            FMA2(aX[k], rA.x, dx[k]); FMA2(aX[k], rA.y, dy[k]); FMA2(aX[k], rB.x, dz[k]);
            FMA2(aY[k], rB.y, dx[k]); FMA2(aY[k], rC.x, dy[k]); FMA2(aY[k], rC.y, dz[k]);
            FMA2(aZ[k], rD.x, dx[k]); FMA2(aZ[k], rD.y, dy[k]); FMA2(aZ[k], rE,   dz[k]);
        }
    }

    // ---- epilogue: split pair halves, add Msum @ base + trans, store ----
    #pragma unroll
    for (int par = 0; par < 2; ++par) {
        float ax[2], ay[2], az[2];
        #pragma unroll
        for (int k = 0; k < 2; ++k) {
            float e, o_;
            UNPK(e, o_, aX[k]); ax[k] = par ? o_ : e;
            UNPK(e, o_, aY[k]); ay[k] = par ? o_ : e;
            UNPK(e, o_, aZ[k]); az[k] = par ? o_ : e;
        }

        const int bsl = 2 * warp + par;            // local bs in [0,16)
        const float* mt = s_Mt + bsl * 12;
        const float M0 = mt[0], M1 = mt[1], M2 = mt[2];
        const float M3 = mt[3], M4 = mt[4], M5 = mt[5];
        const float M6 = mt[6], M7 = mt[7], M8 = mt[8];
        const float T0 = mt[9], T1 = mt[10], T2 = mt[11];

        float r[6];
        #pragma unroll
        for (int k = 0; k < 2; ++k) {
            r[3*k+0] = ax[k] + M0*bx[k] + M1*by[k] + M2*bz[k] + T0;
            r[3*k+1] = ay[k] + M3*bx[k] + M4*by[k] + M5*bz[k] + T1;
            r[3*k+2] = az[k] + M6*bx[k] + M7*by[k] + M8*bz[k] + T2;
        }

        const int gbs = bsb * BSB + bsl;
        const size_t obase = ((size_t)gbs * V_N + v0 + vloc) * 3;
        if (full) {
            float2* o2 = (float2*)(out + obase);   // 8B-aligned (index always even)
            #pragma unroll
            for (int j = 0; j < 3; ++j) o2[j] = make_float2(r[2*j], r[2*j+1]);
        } else {
            #pragma unroll
            for (int k = 0; k < 2; ++k) {
                if (v0 + vloc + k < V_N) {
                    out[obase + 3*k + 0] = r[3*k+0];
                    out[obase + 3*k + 1] = r[3*k+1];
                    out[obase + 3*k + 2] = r[3*k+2];
                }
            }
        }
    }
}

// ---------------------------------------------------------------------------
extern "C" void kernel_launch(void* const* d_in, const int* in_sizes, int n_in,
                              void* d_out, int out_size)
{
    (void)in_sizes; (void)n_in; (void)out_size;
    const float* scales     = (const float*)d_in[0];  // (B,S,1)
    const float* transforms = (const float*)d_in[1];  // (B,S,P,6)
    const float* pw         = (const float*)d_in[2];  // (B,S,P)
    const float* off        = (const float*)d_in[3];  // (P,V,3)
    const float* base       = (const float*)d_in[4];  // (V,3)
    float* out = (float*)d_out;

    rot_kernel<<<B_S, P_N>>>(scales, transforms, pw);

    cudaFuncSetAttribute(mesh_kernel,
                         cudaFuncAttributeMaxDynamicSharedMemorySize, SMEM_BYTES);
    dim3 grid((V_N + VT - 1) / VT, B_S / BSB);   // (41, 16) = 656 CTAs
    mesh_kernel<<<grid, 256, SMEM_BYTES>>>(off, base, out);
}

// round 9
// speedup vs baseline: 4.5716x; 1.7368x over previous
#include <cuda_runtime.h>
#include <cuda_bf16.h>
#include <cstdint>

#define B_S   256
#define P_N   64
#define V_N   2562
#define VPAD  2688          // 21*128, zero-padded tail rows
#define KP    640           // K' = 3*192 + 64 (trans chunk)
#define NCH   10            // K chunks of 64 bf16 (128B rows)
#define M_T   128           // v rows per CTA
#define N_T   64            // n cols per CTA (one i, 64 bs)

// ---- scratch (zero-initialized device globals; no runtime alloc) ----
__device__ __align__(16) __nv_bfloat16 g_def[(size_t)VPAD * KP];     // ~3.4MB
__device__ __align__(16) __nv_bfloat16 g_B[(size_t)3 * B_S * KP];    // ~1MB

__device__ __forceinline__ uint32_t smem_u32(const void* p) {
    uint32_t a;
    asm("{ .reg .u64 t; cvta.to.shared.u64 t, %1; cvt.u32.u64 %0, t; }" : "=r"(a) : "l"(p));
    return a;
}
__device__ __forceinline__ uint32_t sw128(uint32_t x) { return x ^ ((x >> 3) & 0x70); }

#define LDSM4(r, addr) \
    asm volatile("ldmatrix.sync.aligned.m8n8.x4.shared.b16 {%0,%1,%2,%3}, [%4];" \
        : "=r"((r)[0]), "=r"((r)[1]), "=r"((r)[2]), "=r"((r)[3]) : "r"(addr))

#define MMA(d, a, b0, b1) \
    asm volatile("mma.sync.aligned.m16n8k16.row.col.f32.bf16.bf16.f32 " \
        "{%0,%1,%2,%3}, {%4,%5,%6,%7}, {%8,%9}, {%0,%1,%2,%3};" \
        : "+f"((d)[0]), "+f"((d)[1]), "+f"((d)[2]), "+f"((d)[3]) \
        : "r"((a)[0]), "r"((a)[1]), "r"((a)[2]), "r"((a)[3]), "r"(b0), "r"(b1))

// ---------------------------------------------------------------------------
// Prep 1: Â[v, k'] = [hi(def) | lo(def) | hi(def) | 1,1,0...] as bf16
// ---------------------------------------------------------------------------
__global__ __launch_bounds__(192) void defsplit_kernel(
    const float* __restrict__ off, const float* __restrict__ base)
{
    const int v = blockIdx.x;
    const int k = threadIdx.x;        // 0..191 = p*3+j
    const int p = k / 3, j = k - 3 * p;
    const float d = base[v * 3 + j] + off[((size_t)p * V_N + v) * 3 + j];
    const __nv_bfloat16 hi = __float2bfloat16(d);
    const __nv_bfloat16 lo = __float2bfloat16(d - __bfloat162float(hi));
    __nv_bfloat16* row = g_def + (size_t)v * KP;
    row[k] = hi; row[192 + k] = lo; row[384 + k] = hi;
    if (k < 2) row[576 + k] = __float2bfloat16(1.0f);   // trans chunk: A = 1.0, 1.0
}

// ---------------------------------------------------------------------------
// Prep 2: B̂[(i,bs), k'] = [hi(Rws) | hi(Rws) | lo(Rws) | trans_hi, trans_lo]
// ---------------------------------------------------------------------------
__global__ __launch_bounds__(P_N) void rot_kernel(
    const float* __restrict__ scales,
    const float* __restrict__ transforms,
    const float* __restrict__ pw)
{
    const int bs = blockIdx.x;
    const int p  = threadIdx.x;

    const float* t = transforms + ((size_t)bs * P_N + p) * 6;
    const float w  = pw[bs * P_N + p];
    const float ws = w * scales[bs];

    float sx, cx, sy, cy, sz, cz;
    sincosf(t[3], &sx, &cx);
    sincosf(t[4], &sy, &cy);
    sincosf(t[5], &sz, &cz);

    float m[9];
    m[0] = cy*cz;            m[1] = -cy*sz;           m[2] = sy;
    m[3] = cx*sz + sx*sy*cz; m[4] = cx*cz - sx*sy*sz; m[5] = -sx*cy;
    m[6] = sx*sz - cx*sy*cz; m[7] = sx*cz + cx*sy*sz; m[8] = cx*cy;

    #pragma unroll
    for (int i = 0; i < 3; ++i) {
        __nv_bfloat16* row = g_B + ((size_t)i * B_S + bs) * KP;
        #pragma unroll
        for (int j = 0; j < 3; ++j) {
            const float val = m[i * 3 + j] * ws;
            const __nv_bfloat16 hi = __float2bfloat16(val);
            const __nv_bfloat16 lo = __float2bfloat16(val - __bfloat162float(hi));
            const int k = p * 3 + j;
            row[k] = hi; row[192 + k] = hi; row[384 + k] = lo;
        }
    }

    __shared__ float red[P_N][4];
    red[p][0] = w * t[0]; red[p][1] = w * t[1]; red[p][2] = w * t[2];
    __syncthreads();
    if (p < 3) {
        float s = 0.f;
        for (int q = 0; q < P_N; ++q) s += red[q][p];
        const __nv_bfloat16 hi = __float2bfloat16(s);
        const __nv_bfloat16 lo = __float2bfloat16(s - __bfloat162float(hi));
        __nv_bfloat16* row = g_B + ((size_t)p * B_S + bs) * KP;
        row[576] = hi; row[577] = lo;
    }
}

// ---------------------------------------------------------------------------
// Main GEMM via mma.sync (HMMA): C[v, n] = Â @ B̂ᵀ, per-CTA 128x64, K'=640.
// Grid (21, 12): blockIdx.y -> (i = y/4, bs quarter = y%4). 8 warps 4x2,
// warp = 32x32. Double-buffered 64-wide K chunks, SW128-swizzled smem,
// LDG issued before MMA each iteration for overlap. 2 CTAs/SM, one wave.
// ---------------------------------------------------------------------------
#define SM_A(b)   ((b) * 24576u)             // 16KB A tile
#define SM_B(b)   ((b) * 24576u + 16384u)    // 8KB  B tile
#define SMEM_BYTES 49152

__global__ __launch_bounds__(256, 2) void mesh_gemm_kernel(float* __restrict__ out)
{
    extern __shared__ __align__(1024) char smem[];
    const uint32_t sbase = smem_u32(smem);
    const int tid  = threadIdx.x;
    const int lane = tid & 31;
    const int warp = tid >> 5;
    const int v0   = blockIdx.x * M_T;
    const int nb   = blockIdx.y;
    const int i_   = nb >> 2;                  // output component
    const int bs0  = (nb & 3) * N_T;           // bs quarter base
    const int bRow0 = i_ * B_S + bs0;          // g_B row base

    const int wm = warp & 3;                   // warp row (4) -> 32 v
    const int wn = warp >> 2;                  // warp col (2) -> 32 n

    // ldmatrix lane-address components (PTX ISA m16n8k16 fragment layouts)
    // A (row-major 16x16 tiles): lanes 0-7 rows+0 kb+0 | 8-15 rows+8 kb+0 |
    //                            16-23 rows+0 kb+16 | 24-31 rows+8 kb+16
    const int rowA  = wm * 32 + (lane & 7) + ((lane >> 3) & 1) * 8;
    const int kselA = ((lane >> 4) & 1) * 16;
    // B (K-major [n][k], .col operand, non-trans): lanes 0-7 n+0 kb+0 |
    //   8-15 n+0 kb+16 | 16-23 n+8 kb+0 | 24-31 n+8 kb+16
    const int rowB  = wn * 32 + ((lane >> 4) & 1) * 8 + (lane & 7);
    const int kselB = ((lane >> 3) & 1) * 16;

    float acc[2][4][4];
    #pragma unroll
    for (int mt = 0; mt < 2; ++mt)
        #pragma unroll
        for (int nt = 0; nt < 4; ++nt)
            #pragma unroll
            for (int e = 0; e < 4; ++e) acc[mt][nt][e] = 0.f;

    uint4 st[6];
    // ---- staging helpers: its 0-3 cover A (1024 uint4), its 4-5 cover B (512) ----
    auto ldg_chunk = [&](int c) {
        #pragma unroll
        for (int it = 0; it < 4; ++it) {
            const int jdx = tid + it * 256;           // 0..1023
            const int row = jdx >> 3, u = jdx & 7;
            st[it] = *(const uint4*)(g_def + ((size_t)(v0 + row) * KP + c * 64 + u * 8));
        }
        #pragma unroll
        for (int it = 0; it < 2; ++it) {
            const int jdx = tid + it * 256;           // 0..511
            const int row = jdx >> 3, u = jdx & 7;
            st[4 + it] = *(const uint4*)(g_B + ((size_t)(bRow0 + row) * KP + c * 64 + u * 8));
        }
    };
    auto sts_chunk = [&](int b) {
        #pragma unroll
        for (int it = 0; it < 4; ++it) {
            const int jdx = tid + it * 256;
            const int row = jdx >> 3, u = jdx & 7;
            *(uint4*)(smem + SM_A(b) + sw128(row * 128 + u * 16)) = st[it];
        }
        #pragma unroll
        for (int it = 0; it < 2; ++it) {
            const int jdx = tid + it * 256;
            const int row = jdx >> 3, u = jdx & 7;
            *(uint4*)(smem + SM_B(b) + sw128(row * 128 + u * 16)) = st[4 + it];
        }
    };
    auto compute = [&](int b) {
        const uint32_t sA = sbase + SM_A(b);
        const uint32_t sB = sbase + SM_B(b);
        #pragma unroll
        for (int ks = 0; ks < 4; ++ks) {
            uint32_t a0[4], a1[4], q0[4], q1[4];
            LDSM4(a0, sA + sw128(rowA * 128 + ks * 32 + kselA));
            LDSM4(a1, sA + sw128((rowA + 16) * 128 + ks * 32 + kselA));
            LDSM4(q0, sB + sw128(rowB * 128 + ks * 32 + kselB));          // nt 0,1
            LDSM4(q1, sB + sw128((rowB + 16) * 128 + ks * 32 + kselB));   // nt 2,3
            MMA(acc[0][0], a0, q0[0], q0[1]);  MMA(acc[0][1], a0, q0[2], q0[3]);
            MMA(acc[0][2], a0, q1[0], q1[1]);  MMA(acc[0][3], a0, q1[2], q1[3]);
            MMA(acc[1][0], a1, q0[0], q0[1]);  MMA(acc[1][1], a1, q0[2], q0[3]);
            MMA(acc[1][2], a1, q1[0], q1[1]);  MMA(acc[1][3], a1, q1[2], q1[3]);
        }
    };

    ldg_chunk(0); sts_chunk(0);
    __syncthreads();

    for (int c = 0; c < NCH; ++c) {
        const bool more = (c + 1 < NCH);
        if (more) ldg_chunk(c + 1);          // overlap LDG with MMA
        compute(c & 1);
        if (more) sts_chunk((c + 1) & 1);
        __syncthreads();
    }

    // ---- epilogue: scatter stores (frag c0,c1 -> bs,bs+1 @ v ; c2,c3 @ v+8) ----
    const int g  = lane >> 2;
    const int cq = lane & 3;
    #pragma unroll
    for (int mt = 0; mt < 2; ++mt) {
        const int vA = v0 + wm * 32 + mt * 16 + g;
        const int vB = vA + 8;
        #pragma unroll
        for (int nt = 0; nt < 4; ++nt) {
            const int bs = bs0 + wn * 32 + nt * 8 + 2 * cq;
            const size_t r0 = ((size_t)bs * V_N) * 3 + i_;
            const size_t r1 = ((size_t)(bs + 1) * V_N) * 3 + i_;
            if (vA < V_N) {
                out[r0 + (size_t)vA * 3] = acc[mt][nt][0];
                out[r1 + (size_t)vA * 3] = acc[mt][nt][1];
            }
            if (vB < V_N) {
                out[r0 + (size_t)vB * 3] = acc[mt][nt][2];
                out[r1 + (size_t)vB * 3] = acc[mt][nt][3];
            }
        }
    }
}

// ---------------------------------------------------------------------------
extern "C" void kernel_launch(void* const* d_in, const int* in_sizes, int n_in,
                              void* d_out, int out_size)
{
    (void)in_sizes; (void)n_in; (void)out_size;
    const float* scales     = (const float*)d_in[0];  // (B,S,1)
    const float* transforms = (const float*)d_in[1];  // (B,S,P,6)
    const float* pw         = (const float*)d_in[2];  // (B,S,P)
    const float* off        = (const float*)d_in[3];  // (P,V,3)
    const float* base       = (const float*)d_in[4];  // (V,3)
    float* out = (float*)d_out;

    defsplit_kernel<<<V_N, 192>>>(off, base);
    rot_kernel<<<B_S, P_N>>>(scales, transforms, pw);

    cudaFuncSetAttribute(mesh_gemm_kernel,
                         cudaFuncAttributeMaxDynamicSharedMemorySize, SMEM_BYTES);
    dim3 grid((V_N + M_T - 1) / M_T, 12);   // (21, 12) = 252 CTAs
    mesh_gemm_kernel<<<grid, 256, SMEM_BYTES>>>(out);
}